// round 6
// baseline (speedup 1.0000x reference)
#include <cuda_runtime.h>
#include <cuda_bf16.h>
#include <cstdint>
#include <math.h>

// Problem constants
#define NN 50000
#define EG 800000
// DIM = 128, H = 8, HD = 16

// ---------------- scratch (device globals; no runtime allocation) ----------
__device__ float  g_Q   [(size_t)NN * 128];
__device__ float  g_K   [(size_t)NN * 128];
__device__ float  g_V   [(size_t)NN * 128];
__device__ float  g_HA  [(size_t)NN * 128];   // h_attn
__device__ float  g_h1  [(size_t)NN * 128];
__device__ float  g_hidh[(size_t)NN * 256];
__device__ float  g_wV  [(size_t)NN * 128];
__device__ float  g_z   [(size_t)NN * 8];
__device__ float  g_EA  [(size_t)EG * 128];   // Ee, overwritten in-place with e_attn
__device__ float  g_e1  [(size_t)EG * 128];
__device__ float  g_hide[(size_t)EG * 256];
__device__ double g_sum [4 * 128];
__device__ double g_sq  [4 * 128];
__device__ float  g_bnsc[4 * 128];
__device__ float  g_bnsh[4 * 128];
__device__ float  g_zerobias[128];            // static zeros (never written)

// ---------------- zero accumulators ----------------------------------------
__global__ void k_zero() {
    size_t i = (size_t)blockIdx.x * blockDim.x + threadIdx.x;
    size_t stride = (size_t)gridDim.x * blockDim.x;
    for (size_t j = i; j < (size_t)NN * 128; j += stride) g_wV[j] = 0.f;
    for (size_t j = i; j < (size_t)NN * 8;   j += stride) g_z[j]  = 0.f;
    if (i < 512) { g_sum[i] = 0.0; g_sq[i] = 0.0; }
}

// ============================================================================
// mma.sync bf16 helpers (family-portable PTX)
// ============================================================================
__device__ __forceinline__ uint32_t smem_u32(const void* p) {
    uint32_t a;
    asm("{ .reg .u64 t; cvta.to.shared.u64 t, %1; cvt.u32.u64 %0, t; }"
        : "=r"(a) : "l"(p));
    return a;
}

__device__ __forceinline__ void ldsm_x4(uint32_t addr, uint32_t* r) {
    asm volatile("ldmatrix.sync.aligned.m8n8.x4.shared.b16 {%0,%1,%2,%3}, [%4];"
        : "=r"(r[0]), "=r"(r[1]), "=r"(r[2]), "=r"(r[3]) : "r"(addr));
}

__device__ __forceinline__ void mma_bf16(float* acc, const uint32_t* a, const uint32_t* b) {
    asm volatile(
        "mma.sync.aligned.m16n8k16.row.col.f32.bf16.bf16.f32 "
        "{%0,%1,%2,%3},{%4,%5,%6,%7},{%8,%9},{%0,%1,%2,%3};"
        : "+f"(acc[0]), "+f"(acc[1]), "+f"(acc[2]), "+f"(acc[3])
        : "r"(a[0]), "r"(a[1]), "r"(a[2]), "r"(a[3]), "r"(b[0]), "r"(b[1]));
}

__device__ __forceinline__ void split_pair(float x0, float x1, uint32_t& hi, uint32_t& lo)
{
    __nv_bfloat162 h = __floats2bfloat162_rn(x0, x1);
    float r0 = x0 - __bfloat162float(__low2bfloat16(h));
    float r1 = x1 - __bfloat162float(__high2bfloat16(h));
    __nv_bfloat162 l = __floats2bfloat162_rn(r0, r1);
    hi = *reinterpret_cast<uint32_t*>(&h);
    lo = *reinterpret_cast<uint32_t*>(&l);
}

// ============================================================================
// Pipelined HMMA bf16 3-split GEMM, K = 128 fixed, N-tile = 128 columns.
//   C[:, :128] = [resOp(res) +] Aop(A[:, :128]) @ W[:128, :128] + bias (, relu)
// MMA product loops are swept per-product (hh, hl, lh) so same-accumulator
// HMMAs are 16 instructions apart -> no latency-chain stalls.
// SMEM: A: 2 bufs x (hi+lo) x [128][40] bf16 = 40960 B
//       B: (hi+lo) x [128][136] bf16          = 69632 B   total 110592 B
// => 2 CTAs per SM.
// ============================================================================
#define A_CH_B 10240
#define A_BUF_B 20480
#define B_BASE 40960
#define BB 34816u

__global__ __launch_bounds__(256, 2)
void k_mmgemm(const float* __restrict__ A, int Ald,
              const float* __restrict__ W, int Wld,
              const float* __restrict__ bias, const float* __restrict__ res,
              float* __restrict__ C, int Cld, int M, int relu,
              const float* __restrict__ Asc, const float* __restrict__ Ash,
              const float* __restrict__ Rsc, const float* __restrict__ Rsh)
{
    extern __shared__ char smem[];
    const uint32_t sbase = smem_u32(smem);

    const int tid  = threadIdx.x;
    const int lane = tid & 31;
    const int wid  = tid >> 5;
    const int wm   = wid >> 2;          // 0..1
    const int wn   = wid & 3;           // 0..3

    // ---- load W[0:128, 0:128] once: fp32 -> bf16 hi/lo at [n][k], BS=136
    {
        #pragma unroll
        for (int i = tid; i < 32 * 128; i += 256) {
            int n  = i & 127;
            int k4 = (i >> 7) << 2;
            const float* wp = W + (size_t)k4 * Wld + n;
            float x0 = wp[0];
            float x1 = wp[Wld];
            float x2 = wp[2 * Wld];
            float x3 = wp[3 * Wld];
            uint32_t h01, l01, h23, l23;
            split_pair(x0, x1, h01, l01);
            split_pair(x2, x3, h23, l23);
            uint32_t off = ((uint32_t)n * 136 + k4) * 2u;
            *(uint2*)(smem + B_BASE + off)      = make_uint2(h01, h23);
            *(uint2*)(smem + B_BASE + BB + off) = make_uint2(l01, l23);
        }
    }

    const int tiles = (M + 127) >> 7;

    // ldmatrix lane-address components
    const int a_row = (lane & 15);
    const int a_k   = (lane >> 4) << 3;
    const int b_row = (lane & 7) + ((lane >> 4) << 3);
    const int b_k   = ((lane >> 3) & 1) << 3;

    // prefetch chunk 0 of first tile
    float4 pf[4];
    int t = blockIdx.x;
    if (t < tiles) {
        int m0 = t << 7;
        #pragma unroll
        for (int j = 0; j < 4; j++) {
            int idx = tid + (j << 8);
            int gm = m0 + (idx >> 3); if (gm > M - 1) gm = M - 1;
            pf[j] = *(const float4*)(A + (size_t)gm * Ald + ((idx & 7) << 2));
        }
    }
    int buf = 0;

    for (; t < tiles; t += gridDim.x) {
        const int m0 = t << 7;
        float acc[4][4][4] = {};
        #pragma unroll
        for (int kc = 0; kc < 4; kc++) {
            const int kb = kc << 5;
            // ---- convert + store prefetched chunk into buf
            {
                char* ah_base = smem + buf * A_BUF_B;
                #pragma unroll
                for (int j = 0; j < 4; j++) {
                    int idx = tid + (j << 8);
                    int row = idx >> 3;
                    int c4  = (idx & 7) << 2;
                    float4 v = pf[j];
                    if (Asc) {
                        float4 sc = *(const float4*)(Asc + kb + c4);
                        float4 sh = *(const float4*)(Ash + kb + c4);
                        v.x = v.x * sc.x + sh.x;
                        v.y = v.y * sc.y + sh.y;
                        v.z = v.z * sc.z + sh.z;
                        v.w = v.w * sc.w + sh.w;
                    }
                    uint32_t h01, l01, h23, l23;
                    split_pair(v.x, v.y, h01, l01);
                    split_pair(v.z, v.w, h23, l23);
                    uint32_t off = ((uint32_t)row * 40 + c4) * 2u;
                    *(uint2*)(ah_base + off)          = make_uint2(h01, h23);
                    *(uint2*)(ah_base + A_CH_B + off) = make_uint2(l01, l23);
                }
            }
            __syncthreads();
            // ---- prefetch next chunk (overlaps with MMA below)
            {
                int kc2 = kc + 1, t2 = t;
                if (kc2 == 4) { kc2 = 0; t2 = t + gridDim.x; }
                if (t2 < tiles) {
                    int m2 = t2 << 7, kb2 = kc2 << 5;
                    #pragma unroll
                    for (int j = 0; j < 4; j++) {
                        int idx = tid + (j << 8);
                        int gm = m2 + (idx >> 3); if (gm > M - 1) gm = M - 1;
                        pf[j] = *(const float4*)(A + (size_t)gm * Ald + kb2 + ((idx & 7) << 2));
                    }
                }
            }
            // ---- MMA over 2 k16-steps of this chunk
            const uint32_t abase = sbase + buf * A_BUF_B;
            #pragma unroll
            for (int ks = 0; ks < 2; ks++) {
                const int ka = ks << 4;
                uint32_t bh[4][2], bl[4][2];
                #pragma unroll
                for (int np = 0; np < 2; np++) {
                    uint32_t roff = ((uint32_t)(wn * 32 + np * 16 + b_row) * 136
                                     + kb + ka + b_k) * 2u;
                    uint32_t rh[4], rl[4];
                    ldsm_x4(sbase + B_BASE + roff, rh);
                    ldsm_x4(sbase + B_BASE + BB + roff, rl);
                    bh[np*2][0] = rh[0]; bh[np*2][1] = rh[1];
                    bh[np*2+1][0] = rh[2]; bh[np*2+1][1] = rh[3];
                    bl[np*2][0] = rl[0]; bl[np*2][1] = rl[1];
                    bl[np*2+1][0] = rl[2]; bl[np*2+1][1] = rl[3];
                }
                uint32_t ah[4][4], al[4][4];
                #pragma unroll
                for (int mt = 0; mt < 4; mt++) {
                    uint32_t roff = ((uint32_t)(wm * 64 + mt * 16 + a_row) * 40
                                     + ka + a_k) * 2u;
                    ldsm_x4(abase + roff, ah[mt]);
                    ldsm_x4(abase + A_CH_B + roff, al[mt]);
                }
                // three product sweeps: same-acc MMAs are 16 apart
                #pragma unroll
                for (int mt = 0; mt < 4; mt++)
                    #pragma unroll
                    for (int nt = 0; nt < 4; nt++)
                        mma_bf16(acc[mt][nt], ah[mt], bh[nt]);
                #pragma unroll
                for (int mt = 0; mt < 4; mt++)
                    #pragma unroll
                    for (int nt = 0; nt < 4; nt++)
                        mma_bf16(acc[mt][nt], ah[mt], bl[nt]);
                #pragma unroll
                for (int mt = 0; mt < 4; mt++)
                    #pragma unroll
                    for (int nt = 0; nt < 4; nt++)
                        mma_bf16(acc[mt][nt], al[mt], bh[nt]);
            }
            buf ^= 1;
        }

        // ---- epilogue
        const int g  = lane >> 2;
        const int t2 = (lane & 3) << 1;
        #pragma unroll
        for (int mt = 0; mt < 4; mt++) {
            int r0 = m0 + wm * 64 + mt * 16 + g;
            #pragma unroll
            for (int nt = 0; nt < 4; nt++) {
                int c0 = wn * 32 + nt * 8 + t2;
                float2 bv = *(const float2*)(bias + c0);
                #pragma unroll
                for (int half = 0; half < 2; half++) {
                    int r = r0 + half * 8;
                    if (r >= M) continue;
                    size_t o = (size_t)r * Cld + c0;
                    float2 v = make_float2(acc[mt][nt][half*2]   + bv.x,
                                           acc[mt][nt][half*2+1] + bv.y);
                    if (res) {
                        float2 rv = *(const float2*)(res + o);
                        if (Rsc) {
                            float2 rs = *(const float2*)(Rsc + c0);
                            float2 rb = *(const float2*)(Rsh + c0);
                            rv.x = rv.x * rs.x + rb.x;
                            rv.y = rv.y * rs.y + rb.y;
                        }
                        v.x += rv.x; v.y += rv.y;
                    }
                    if (relu) { v.x = fmaxf(v.x, 0.f); v.y = fmaxf(v.y, 0.f); }
                    *(float2*)(C + o) = v;
                }
            }
        }
    }
}

// ---------------- edge kernel: score, e_attn (in place), s, segment sums ---
__global__ __launch_bounds__(256)
void k_edge(const int* __restrict__ src, const int* __restrict__ dst)
{
    const int t = threadIdx.x & 127;
    const int e = blockIdx.x * 2 + (threadIdx.x >> 7);
    if (e >= EG) return;
    const int s = src[e];
    const int d = dst[e];
    float sc = g_K[(size_t)s * 128 + t] * g_Q[(size_t)d * 128 + t] * 0.25f
             * g_EA[(size_t)e * 128 + t];
    g_EA[(size_t)e * 128 + t] = sc;
    float sum = sc;
    #pragma unroll
    for (int off = 8; off; off >>= 1)
        sum += __shfl_xor_sync(0xffffffffu, sum, off, 16);
    sum = fminf(fmaxf(sum, -5.f), 5.f);
    float ss = __expf(sum);
    atomicAdd(&g_wV[(size_t)d * 128 + t], g_V[(size_t)s * 128 + t] * ss);
    if ((t & 15) == 0)
        atomicAdd(&g_z[(size_t)d * 8 + (t >> 4)], ss);
}

// ---------------- h_attn = wV / (z + 1e-6) ----------------------------------
__global__ void k_hattn()
{
    size_t i = (size_t)blockIdx.x * blockDim.x + threadIdx.x;
    if (i >= (size_t)NN * 128) return;
    int c = (int)(i & 127);
    size_t n = i >> 7;
    g_HA[i] = g_wV[i] / (g_z[n * 8 + (c >> 4)] + 1e-6f);
}

// ---------------- batch-norm ------------------------------------------------
__global__ __launch_bounds__(256)
void k_bn_reduce(const float* __restrict__ X, int M, int slot)
{
    int c  = threadIdx.x & 127;
    int r0 = blockIdx.x * 2 + (threadIdx.x >> 7);
    double s = 0.0, q = 0.0;
    for (int r = r0; r < M; r += gridDim.x * 2) {
        float v = X[(size_t)r * 128 + c];
        s += v;
        q += (double)v * v;
    }
    atomicAdd(&g_sum[slot * 128 + c], s);
    atomicAdd(&g_sq [slot * 128 + c], q);
}

__global__ void k_bn_finalize(int slot, float Mf,
                              const float* __restrict__ g, const float* __restrict__ b)
{
    int c = threadIdx.x;
    double mu  = g_sum[slot * 128 + c] / (double)Mf;
    double var = g_sq [slot * 128 + c] / (double)Mf - mu * mu;
    float sc = g[c] * rsqrtf((float)var + 1e-5f);
    g_bnsc[slot * 128 + c] = sc;
    g_bnsh[slot * 128 + c] = b[c] - (float)mu * sc;
}

__global__ __launch_bounds__(256)
void k_bn_apply(float* __restrict__ X, size_t M, int slot)
{
    size_t total4 = M * 32;
    size_t i = (size_t)blockIdx.x * blockDim.x + threadIdx.x;
    size_t stride = (size_t)gridDim.x * blockDim.x;
    for (size_t j = i; j < total4; j += stride) {
        int c = (int)(j & 31) * 4;
        const float* sc = g_bnsc + slot * 128 + c;
        const float* sh = g_bnsh + slot * 128 + c;
        float4 v = ((float4*)X)[j];
        v.x = v.x * sc[0] + sh[0];
        v.y = v.y * sc[1] + sh[1];
        v.z = v.z * sc[2] + sh[2];
        v.w = v.w * sc[3] + sh[3];
        ((float4*)X)[j] = v;
    }
}

// ---------------- host orchestration ---------------------------------------
#define GEMM_SMEM 110592

static void mm128(const float* A, int Ald, const float* W, int Wld,
                  const float* bias, const float* res, float* C, int Cld,
                  int M, int relu,
                  const float* Asc = nullptr, const float* Ash = nullptr,
                  const float* Rsc = nullptr, const float* Rsh = nullptr)
{
    int tiles = (M + 127) / 128;
    int grid = tiles < 296 ? tiles : 296;
    k_mmgemm<<<grid, 256, GEMM_SMEM>>>(A, Ald, W, Wld, bias, res, C, Cld, M, relu,
                                       Asc, Ash, Rsc, Rsh);
}

extern "C" void kernel_launch(void* const* d_in, const int* in_sizes, int n_in,
                              void* d_out, int out_size)
{
    const float* h   = (const float*)d_in[0];
    const float* e   = (const float*)d_in[1];
    const int*   src = (const int*)d_in[2];
    const int*   dst = (const int*)d_in[3];
    const float* WQ  = (const float*)d_in[4];   const float* bQ  = (const float*)d_in[5];
    const float* WK  = (const float*)d_in[6];   const float* bK  = (const float*)d_in[7];
    const float* WV  = (const float*)d_in[8];   const float* bV  = (const float*)d_in[9];
    const float* WE  = (const float*)d_in[10];  const float* bE  = (const float*)d_in[11];
    const float* WOh = (const float*)d_in[12];  const float* bOh = (const float*)d_in[13];
    const float* WOe = (const float*)d_in[14];  const float* bOe = (const float*)d_in[15];
    const float* Wh1 = (const float*)d_in[16];  const float* bh1 = (const float*)d_in[17];
    const float* Wh2 = (const float*)d_in[18];  const float* bh2 = (const float*)d_in[19];
    const float* We1 = (const float*)d_in[20];  const float* be1 = (const float*)d_in[21];
    const float* We2 = (const float*)d_in[22];  const float* be2 = (const float*)d_in[23];
    const float* g1h = (const float*)d_in[24];
    const float* g1e = (const float*)d_in[25];
    const float* g2h = (const float*)d_in[26];
    const float* g2e = (const float*)d_in[27];
    const float* b1h = (const float*)d_in[28];
    const float* b1e = (const float*)d_in[29];
    const float* b2h = (const float*)d_in[30];
    const float* b2e = (const float*)d_in[31];

    float *pQ, *pK, *pV, *pHA, *ph1, *phidh, *pEA, *pe1, *phide, *pbnsc, *pbnsh, *pzb;
    cudaGetSymbolAddress((void**)&pQ,    g_Q);
    cudaGetSymbolAddress((void**)&pK,    g_K);
    cudaGetSymbolAddress((void**)&pV,    g_V);
    cudaGetSymbolAddress((void**)&pHA,   g_HA);
    cudaGetSymbolAddress((void**)&ph1,   g_h1);
    cudaGetSymbolAddress((void**)&phidh, g_hidh);
    cudaGetSymbolAddress((void**)&pEA,   g_EA);
    cudaGetSymbolAddress((void**)&pe1,   g_e1);
    cudaGetSymbolAddress((void**)&phide, g_hide);
    cudaGetSymbolAddress((void**)&pbnsc, g_bnsc);
    cudaGetSymbolAddress((void**)&pbnsh, g_bnsh);
    cudaGetSymbolAddress((void**)&pzb,   g_zerobias);

    cudaFuncSetAttribute(k_mmgemm, cudaFuncAttributeMaxDynamicSharedMemorySize, GEMM_SMEM);

    float* out_h = (float*)d_out;                       // [NN,128]
    float* out_e = (float*)d_out + (size_t)NN * 128;    // [EG,128]

    // 0) zero accumulators + BN stats
    k_zero<<<4096, 256>>>();

    // 1) projections
    mm128(h, 128, WQ, 128, bQ, nullptr, pQ,  128, NN, 0);
    mm128(h, 128, WK, 128, bK, nullptr, pK,  128, NN, 0);
    mm128(h, 128, WV, 128, bV, nullptr, pV,  128, NN, 0);
    mm128(e, 128, WE, 128, bE, nullptr, pEA, 128, EG, 0);

    // 2) edge scores + attention weights + segment sums (atomics)
    k_edge<<<EG / 2, 256>>>(src, dst);

    // 3) h_attn
    k_hattn<<<(NN * 128 + 255) / 256, 256>>>();

    // 4) O projections with residual
    mm128(pHA, 128, WOh, 128, bOh, h, ph1, 128, NN, 0);
    mm128(pEA, 128, WOe, 128, bOe, e, pe1, 128, EG, 0);

    // 5) BN #1 stats (apply fused into FFN GEMMs)
    k_bn_reduce<<<1024, 256>>>(ph1, NN, 0);
    k_bn_finalize<<<1, 128>>>(0, (float)NN, g1h, b1h);
    k_bn_reduce<<<2048, 256>>>(pe1, EG, 1);
    k_bn_finalize<<<1, 128>>>(1, (float)EG, g1e, b1e);

    // 6) FFNs. FFN1: Nc=256 as two column halves, A-side BN fused.
    //    FFN2: K=256 as two K=128 accumulation passes, res-side BN fused in pass1.
    // h-side
    mm128(ph1, 128, Wh1,       256, bh1,       nullptr, phidh,       256, NN, 1,
          pbnsc + 0, pbnsh + 0);
    mm128(ph1, 128, Wh1 + 128, 256, bh1 + 128, nullptr, phidh + 128, 256, NN, 1,
          pbnsc + 0, pbnsh + 0);
    mm128(phidh,       256, Wh2,             128, bh2, ph1,   out_h, 128, NN, 0,
          nullptr, nullptr, pbnsc + 0, pbnsh + 0);
    mm128(phidh + 128, 256, Wh2 + 128 * 128, 128, pzb, out_h, out_h, 128, NN, 0);
    // e-side
    mm128(pe1, 128, We1,       256, be1,       nullptr, phide,       256, EG, 1,
          pbnsc + 128, pbnsh + 128);
    mm128(pe1, 128, We1 + 128, 256, be1 + 128, nullptr, phide + 128, 256, EG, 1,
          pbnsc + 128, pbnsh + 128);
    mm128(phide,       256, We2,             128, be2, pe1,   out_e, 128, EG, 0,
          nullptr, nullptr, pbnsc + 128, pbnsh + 128);
    mm128(phide + 128, 256, We2 + 128 * 128, 128, pzb, out_e, out_e, 128, EG, 0);

    // 7) BN #2 (in place on the output buffer)
    k_bn_reduce<<<1024, 256>>>(out_h, NN, 2);
    k_bn_finalize<<<1, 128>>>(2, (float)NN, g2h, b2h);
    k_bn_apply<<<12800, 256>>>(out_h, (size_t)NN, 2);
    k_bn_reduce<<<2048, 256>>>(out_e, EG, 3);
    k_bn_finalize<<<1, 128>>>(3, (float)EG, g2e, b2e);
    k_bn_apply<<<100000, 256>>>(out_e, (size_t)EG, 3);
}

// round 7
// speedup vs baseline: 1.3264x; 1.3264x over previous
#include <cuda_runtime.h>
#include <cuda_bf16.h>
#include <cstdint>
#include <math.h>

// Problem constants
#define NN 50000
#define EG 800000
// DIM = 128, H = 8, HD = 16

// ---------------- scratch (device globals; no runtime allocation) ----------
__device__ float  g_Q   [(size_t)NN * 128];
__device__ float  g_K   [(size_t)NN * 128];
__device__ float  g_V   [(size_t)NN * 128];
__device__ float  g_h1  [(size_t)NN * 128];
__device__ float  g_hidh[(size_t)NN * 256];
__device__ float  g_wV  [(size_t)NN * 128];
__device__ float  g_z   [(size_t)NN * 8];
__device__ float  g_EA  [(size_t)EG * 128];   // Ee, overwritten in-place with e_attn
__device__ float  g_e1  [(size_t)EG * 128];
__device__ float  g_hide[(size_t)EG * 256];
__device__ double g_sum [4 * 128];
__device__ double g_sq  [4 * 128];
__device__ float  g_bnsc[4 * 128];
__device__ float  g_bnsh[4 * 128];

// ---------------- zero accumulators ----------------------------------------
__global__ void k_zero() {
    size_t i = (size_t)blockIdx.x * blockDim.x + threadIdx.x;
    size_t stride = (size_t)gridDim.x * blockDim.x;
    for (size_t j = i; j < (size_t)NN * 128; j += stride) g_wV[j] = 0.f;
    for (size_t j = i; j < (size_t)NN * 8;   j += stride) g_z[j]  = 0.f;
    if (i < 512) { g_sum[i] = 0.0; g_sq[i] = 0.0; }
}

// ============================================================================
// mma.sync bf16 helpers
// ============================================================================
__device__ __forceinline__ uint32_t smem_u32(const void* p) {
    uint32_t a;
    asm("{ .reg .u64 t; cvta.to.shared.u64 t, %1; cvt.u32.u64 %0, t; }"
        : "=r"(a) : "l"(p));
    return a;
}

__device__ __forceinline__ void ldsm_x4(uint32_t addr, uint32_t* r) {
    asm volatile("ldmatrix.sync.aligned.m8n8.x4.shared.b16 {%0,%1,%2,%3}, [%4];"
        : "=r"(r[0]), "=r"(r[1]), "=r"(r[2]), "=r"(r[3]) : "r"(addr));
}

__device__ __forceinline__ void mma_bf16(float* acc, const uint32_t* a, const uint32_t* b) {
    asm volatile(
        "mma.sync.aligned.m16n8k16.row.col.f32.bf16.bf16.f32 "
        "{%0,%1,%2,%3},{%4,%5,%6,%7},{%8,%9},{%0,%1,%2,%3};"
        : "+f"(acc[0]), "+f"(acc[1]), "+f"(acc[2]), "+f"(acc[3])
        : "r"(a[0]), "r"(a[1]), "r"(a[2]), "r"(a[3]), "r"(b[0]), "r"(b[1]));
}

__device__ __forceinline__ void split_pair(float x0, float x1, uint32_t& hi, uint32_t& lo)
{
    __nv_bfloat162 h = __floats2bfloat162_rn(x0, x1);
    float r0 = x0 - __bfloat162float(__low2bfloat16(h));
    float r1 = x1 - __bfloat162float(__high2bfloat16(h));
    __nv_bfloat162 l = __floats2bfloat162_rn(r0, r1);
    hi = *reinterpret_cast<uint32_t*>(&h);
    lo = *reinterpret_cast<uint32_t*>(&l);
}

// ============================================================================
// Pipelined HMMA bf16 3-split GEMM. K = KC*32 (KC=4 or 8), N-tile = 128.
//   C = [res(*RscRsh) +] (A(*AscAsh)(/Zrow)) @ W + bias (, relu)
// Optional fused per-column sum/sumsq reduce (sumP/sqP, doubles).
// SMEM: A 2 bufs x (hi+lo) x [128][40] = 40960 B
//       B (hi+lo) x [128][K+8] bf16
// ============================================================================
#define A_CH_B 10240
#define A_BUF_B 20480
#define B_BASE 40960

template<int KC>
__global__ __launch_bounds__(256, (KC == 4) ? 2 : 1)
void k_mmgemm(const float* __restrict__ A, int Ald,
              const float* __restrict__ W, int Wld,
              const float* __restrict__ bias, const float* __restrict__ res,
              float* __restrict__ C, int Cld, int M, int relu,
              const float* __restrict__ Asc, const float* __restrict__ Ash,
              const float* __restrict__ Zrow,
              const float* __restrict__ Rsc, const float* __restrict__ Rsh,
              double* sumP, double* sqP)
{
    extern __shared__ char smem[];
    constexpr int K  = KC * 32;
    constexpr int BS = K + 8;
    constexpr uint32_t BBs = 128u * BS * 2u;
    const uint32_t sbase = smem_u32(smem);

    const int tid  = threadIdx.x;
    const int lane = tid & 31;
    const int wid  = tid >> 5;
    const int wm   = wid >> 2;
    const int wn   = wid & 3;

    // ---- load W[0:K, 0:128]: fp32 -> bf16 hi/lo at [n][k]
    for (int i = tid; i < (K >> 2) * 128; i += 256) {
        int n  = i & 127;
        int k4 = (i >> 7) << 2;
        const float* wp = W + (size_t)k4 * Wld + n;
        float x0 = wp[0];
        float x1 = wp[Wld];
        float x2 = wp[2 * Wld];
        float x3 = wp[3 * Wld];
        uint32_t h01, l01, h23, l23;
        split_pair(x0, x1, h01, l01);
        split_pair(x2, x3, h23, l23);
        uint32_t off = ((uint32_t)n * BS + k4) * 2u;
        *(uint2*)(smem + B_BASE + off)       = make_uint2(h01, h23);
        *(uint2*)(smem + B_BASE + BBs + off) = make_uint2(l01, l23);
    }

    const int tiles = (M + 127) >> 7;

    const int a_row = (lane & 15);
    const int a_k   = (lane >> 4) << 3;
    const int b_row = (lane & 7) + ((lane >> 4) << 3);
    const int b_k   = ((lane >> 3) & 1) << 3;

    float4 pf[4];
    int t = blockIdx.x;
    if (t < tiles) {
        int m0 = t << 7;
        #pragma unroll
        for (int j = 0; j < 4; j++) {
            int idx = tid + (j << 8);
            int gm = m0 + (idx >> 3); if (gm > M - 1) gm = M - 1;
            pf[j] = *(const float4*)(A + (size_t)gm * Ald + ((idx & 7) << 2));
        }
    }
    int buf = 0;

    for (; t < tiles; t += gridDim.x) {
        const int m0 = t << 7;
        float acc[4][4][4] = {};
        for (int kc = 0; kc < KC; kc++) {
            const int kb = kc << 5;
            // ---- convert + store prefetched chunk
            {
                char* ah_base = smem + buf * A_BUF_B;
                #pragma unroll
                for (int j = 0; j < 4; j++) {
                    int idx = tid + (j << 8);
                    int row = idx >> 3;
                    int c4  = (idx & 7) << 2;
                    float4 v = pf[j];
                    if (Asc) {
                        float4 sc = *(const float4*)(Asc + kb + c4);
                        float4 sh = *(const float4*)(Ash + kb + c4);
                        v.x = v.x * sc.x + sh.x;
                        v.y = v.y * sc.y + sh.y;
                        v.z = v.z * sc.z + sh.z;
                        v.w = v.w * sc.w + sh.w;
                    }
                    if (Zrow) {
                        int gm = m0 + row; if (gm > M - 1) gm = M - 1;
                        float zz = 1.0f / (Zrow[(size_t)gm * 8 + ((kb + c4) >> 4)] + 1e-6f);
                        v.x *= zz; v.y *= zz; v.z *= zz; v.w *= zz;
                    }
                    uint32_t h01, l01, h23, l23;
                    split_pair(v.x, v.y, h01, l01);
                    split_pair(v.z, v.w, h23, l23);
                    uint32_t off = ((uint32_t)row * 40 + c4) * 2u;
                    *(uint2*)(ah_base + off)          = make_uint2(h01, h23);
                    *(uint2*)(ah_base + A_CH_B + off) = make_uint2(l01, l23);
                }
            }
            __syncthreads();
            // ---- prefetch next chunk
            {
                int kc2 = kc + 1, tn = t;
                if (kc2 == KC) { kc2 = 0; tn = t + gridDim.x; }
                if (tn < tiles) {
                    int m2 = tn << 7, kb2 = kc2 << 5;
                    #pragma unroll
                    for (int j = 0; j < 4; j++) {
                        int idx = tid + (j << 8);
                        int gm = m2 + (idx >> 3); if (gm > M - 1) gm = M - 1;
                        pf[j] = *(const float4*)(A + (size_t)gm * Ald + kb2 + ((idx & 7) << 2));
                    }
                }
            }
            // ---- MMA over 2 k16-steps
            const uint32_t abase = sbase + buf * A_BUF_B;
            #pragma unroll
            for (int ks = 0; ks < 2; ks++) {
                const int ka = ks << 4;
                uint32_t bh[4][2], bl[4][2];
                #pragma unroll
                for (int np = 0; np < 2; np++) {
                    uint32_t roff = ((uint32_t)(wn * 32 + np * 16 + b_row) * BS
                                     + kb + ka + b_k) * 2u;
                    uint32_t rh[4], rl[4];
                    ldsm_x4(sbase + B_BASE + roff, rh);
                    ldsm_x4(sbase + B_BASE + BBs + roff, rl);
                    bh[np*2][0] = rh[0]; bh[np*2][1] = rh[1];
                    bh[np*2+1][0] = rh[2]; bh[np*2+1][1] = rh[3];
                    bl[np*2][0] = rl[0]; bl[np*2][1] = rl[1];
                    bl[np*2+1][0] = rl[2]; bl[np*2+1][1] = rl[3];
                }
                uint32_t ah[4][4], al[4][4];
                #pragma unroll
                for (int mt = 0; mt < 4; mt++) {
                    uint32_t roff = ((uint32_t)(wm * 64 + mt * 16 + a_row) * 40
                                     + ka + a_k) * 2u;
                    ldsm_x4(abase + roff, ah[mt]);
                    ldsm_x4(abase + A_CH_B + roff, al[mt]);
                }
                #pragma unroll
                for (int mt = 0; mt < 4; mt++)
                    #pragma unroll
                    for (int nt = 0; nt < 4; nt++) {
                        mma_bf16(acc[mt][nt], ah[mt], bh[nt]);
                        mma_bf16(acc[mt][nt], ah[mt], bl[nt]);
                        mma_bf16(acc[mt][nt], al[mt], bh[nt]);
                    }
            }
            buf ^= 1;
        }

        // ---- epilogue (per nt: write + optional column reduce)
        const int g  = lane >> 2;
        const int t2 = (lane & 3) << 1;
        #pragma unroll
        for (int nt = 0; nt < 4; nt++) {
            int c0 = wn * 32 + nt * 8 + t2;
            float2 bv = *(const float2*)(bias + c0);
            float2 rs = make_float2(1.f, 1.f), rb = make_float2(0.f, 0.f);
            if (Rsc) {
                rs = *(const float2*)(Rsc + c0);
                rb = *(const float2*)(Rsh + c0);
            }
            float ps0 = 0.f, ps1 = 0.f, q0 = 0.f, q1 = 0.f;
            #pragma unroll
            for (int mt = 0; mt < 4; mt++) {
                #pragma unroll
                for (int half = 0; half < 2; half++) {
                    int r = m0 + wm * 64 + mt * 16 + g + half * 8;
                    float2 v = make_float2(acc[mt][nt][half*2]   + bv.x,
                                           acc[mt][nt][half*2+1] + bv.y);
                    if (r < M) {
                        size_t o = (size_t)r * Cld + c0;
                        if (res) {
                            float2 rv = *(const float2*)(res + o);
                            v.x += rv.x * rs.x + rb.x;
                            v.y += rv.y * rs.y + rb.y;
                        }
                        if (relu) { v.x = fmaxf(v.x, 0.f); v.y = fmaxf(v.y, 0.f); }
                        *(float2*)(C + o) = v;
                    } else { v.x = 0.f; v.y = 0.f; }
                    ps0 += v.x; q0 += v.x * v.x;
                    ps1 += v.y; q1 += v.y * v.y;
                }
            }
            if (sumP) {
                #pragma unroll
                for (int off = 16; off >= 4; off >>= 1) {
                    ps0 += __shfl_down_sync(0xffffffffu, ps0, off);
                    ps1 += __shfl_down_sync(0xffffffffu, ps1, off);
                    q0  += __shfl_down_sync(0xffffffffu, q0,  off);
                    q1  += __shfl_down_sync(0xffffffffu, q1,  off);
                }
                if (lane < 4) {
                    int cc = wn * 32 + nt * 8 + lane * 2;
                    atomicAdd(&sumP[cc],     (double)ps0);
                    atomicAdd(&sumP[cc + 1], (double)ps1);
                    atomicAdd(&sqP[cc],      (double)q0);
                    atomicAdd(&sqP[cc + 1],  (double)q1);
                }
            }
        }
    }
}

// ============================================================================
// FFN1: C[M,256] = relu( (A(*AscAsh)) @ W[128,256] + bias ), single launch.
// A tile resident [128][136] hi/lo (69.6KB), B [256][136] hi/lo (139.3KB).
// ============================================================================
#define F1_A_LO 34816
#define F1_B    69632
#define F1_BBs  69632u

__global__ __launch_bounds__(256, 1)
void k_ffn1(const float* __restrict__ A, const float* __restrict__ W,
            const float* __restrict__ bias, float* __restrict__ C, int M,
            const float* __restrict__ Asc, const float* __restrict__ Ash)
{
    extern __shared__ char smem[];
    const uint32_t sbase = smem_u32(smem);
    const int tid  = threadIdx.x;
    const int lane = tid & 31;
    const int wid  = tid >> 5;
    const int wm   = wid >> 2;
    const int wn   = wid & 3;

    // ---- load W [128][256] -> [n=256][k=136] hi/lo
    for (int i = tid; i < 32 * 256; i += 256) {
        int n  = i & 255;
        int k4 = (i >> 8) << 2;
        const float* wp = W + (size_t)k4 * 256 + n;
        float x0 = wp[0];
        float x1 = wp[256];
        float x2 = wp[512];
        float x3 = wp[768];
        uint32_t h01, l01, h23, l23;
        split_pair(x0, x1, h01, l01);
        split_pair(x2, x3, h23, l23);
        uint32_t off = ((uint32_t)n * 136 + k4) * 2u;
        *(uint2*)(smem + F1_B + off)           = make_uint2(h01, h23);
        *(uint2*)(smem + F1_B + F1_BBs + off)  = make_uint2(l01, l23);
    }

    const int tiles = (M + 127) >> 7;
    const int a_row = (lane & 15);
    const int a_k   = (lane >> 4) << 3;
    const int b_row = (lane & 7) + ((lane >> 4) << 3);
    const int b_k   = ((lane >> 3) & 1) << 3;
    const int g  = lane >> 2;
    const int t2 = (lane & 3) << 1;

    for (int t = blockIdx.x; t < tiles; t += gridDim.x) {
        const int m0 = t << 7;
        __syncthreads();
        // ---- stage full A tile [128][128] -> [128][136] hi/lo
        for (int j = 0; j < 16; j++) {
            int idx = tid + (j << 8);
            int row = idx >> 5;
            int c4  = (idx & 31) << 2;
            int gm = m0 + row; if (gm > M - 1) gm = M - 1;
            float4 v = *(const float4*)(A + (size_t)gm * 128 + c4);
            float4 sc = *(const float4*)(Asc + c4);
            float4 sh = *(const float4*)(Ash + c4);
            v.x = v.x * sc.x + sh.x;
            v.y = v.y * sc.y + sh.y;
            v.z = v.z * sc.z + sh.z;
            v.w = v.w * sc.w + sh.w;
            uint32_t h01, l01, h23, l23;
            split_pair(v.x, v.y, h01, l01);
            split_pair(v.z, v.w, h23, l23);
            uint32_t off = ((uint32_t)row * 136 + c4) * 2u;
            *(uint2*)(smem + off)           = make_uint2(h01, h23);
            *(uint2*)(smem + F1_A_LO + off) = make_uint2(l01, l23);
        }
        __syncthreads();

        for (int nh = 0; nh < 2; nh++) {
            float acc[4][4][4] = {};
            #pragma unroll
            for (int ks = 0; ks < 8; ks++) {
                const int ka = ks << 4;
                uint32_t bh[4][2], bl[4][2];
                #pragma unroll
                for (int np = 0; np < 2; np++) {
                    uint32_t roff = ((uint32_t)(nh * 128 + wn * 32 + np * 16 + b_row) * 136
                                     + ka + b_k) * 2u;
                    uint32_t rh[4], rl[4];
                    ldsm_x4(sbase + F1_B + roff, rh);
                    ldsm_x4(sbase + F1_B + F1_BBs + roff, rl);
                    bh[np*2][0] = rh[0]; bh[np*2][1] = rh[1];
                    bh[np*2+1][0] = rh[2]; bh[np*2+1][1] = rh[3];
                    bl[np*2][0] = rl[0]; bl[np*2][1] = rl[1];
                    bl[np*2+1][0] = rl[2]; bl[np*2+1][1] = rl[3];
                }
                uint32_t ah[4][4], al[4][4];
                #pragma unroll
                for (int mt = 0; mt < 4; mt++) {
                    uint32_t roff = ((uint32_t)(wm * 64 + mt * 16 + a_row) * 136
                                     + ka + a_k) * 2u;
                    ldsm_x4(sbase + roff, ah[mt]);
                    ldsm_x4(sbase + F1_A_LO + roff, al[mt]);
                }
                #pragma unroll
                for (int mt = 0; mt < 4; mt++)
                    #pragma unroll
                    for (int nt = 0; nt < 4; nt++) {
                        mma_bf16(acc[mt][nt], ah[mt], bh[nt]);
                        mma_bf16(acc[mt][nt], ah[mt], bl[nt]);
                        mma_bf16(acc[mt][nt], al[mt], bh[nt]);
                    }
            }
            // epilogue (relu, no res)
            #pragma unroll
            for (int mt = 0; mt < 4; mt++) {
                int r0 = m0 + wm * 64 + mt * 16 + g;
                #pragma unroll
                for (int nt = 0; nt < 4; nt++) {
                    int c0 = nh * 128 + wn * 32 + nt * 8 + t2;
                    float2 bv = *(const float2*)(bias + c0);
                    #pragma unroll
                    for (int half = 0; half < 2; half++) {
                        int r = r0 + half * 8;
                        if (r >= M) continue;
                        float2 v = make_float2(
                            fmaxf(acc[mt][nt][half*2]   + bv.x, 0.f),
                            fmaxf(acc[mt][nt][half*2+1] + bv.y, 0.f));
                        *(float2*)(C + (size_t)r * 256 + c0) = v;
                    }
                }
            }
        }
    }
}

// ---------------- edge kernel: score, e_attn (in place), s, segment sums ---
__global__ __launch_bounds__(256)
void k_edge(const int* __restrict__ src, const int* __restrict__ dst)
{
    const int t = threadIdx.x & 127;
    const int e = blockIdx.x * 2 + (threadIdx.x >> 7);
    if (e >= EG) return;
    const int s = src[e];
    const int d = dst[e];
    float sc = g_K[(size_t)s * 128 + t] * g_Q[(size_t)d * 128 + t] * 0.25f
             * g_EA[(size_t)e * 128 + t];
    g_EA[(size_t)e * 128 + t] = sc;
    float sum = sc;
    #pragma unroll
    for (int off = 8; off; off >>= 1)
        sum += __shfl_xor_sync(0xffffffffu, sum, off, 16);
    sum = fminf(fmaxf(sum, -5.f), 5.f);
    float ss = __expf(sum);
    atomicAdd(&g_wV[(size_t)d * 128 + t], g_V[(size_t)s * 128 + t] * ss);
    if ((t & 15) == 0)
        atomicAdd(&g_z[(size_t)d * 8 + (t >> 4)], ss);
}

// ---------------- batch-norm finalize / apply --------------------------------
__global__ void k_bn_finalize(int slot, float Mf,
                              const float* __restrict__ g, const float* __restrict__ b)
{
    int c = threadIdx.x;
    double mu  = g_sum[slot * 128 + c] / (double)Mf;
    double var = g_sq [slot * 128 + c] / (double)Mf - mu * mu;
    float sc = g[c] * rsqrtf((float)var + 1e-5f);
    g_bnsc[slot * 128 + c] = sc;
    g_bnsh[slot * 128 + c] = b[c] - (float)mu * sc;
}

__global__ __launch_bounds__(256)
void k_bn_apply(float* __restrict__ X, size_t M, int slot)
{
    size_t total4 = M * 32;
    size_t i = (size_t)blockIdx.x * blockDim.x + threadIdx.x;
    size_t stride = (size_t)gridDim.x * blockDim.x;
    for (size_t j = i; j < total4; j += stride) {
        int c = (int)(j & 31) * 4;
        const float* sc = g_bnsc + slot * 128 + c;
        const float* sh = g_bnsh + slot * 128 + c;
        float4 v = ((float4*)X)[j];
        v.x = v.x * sc[0] + sh[0];
        v.y = v.y * sc[1] + sh[1];
        v.z = v.z * sc[2] + sh[2];
        v.w = v.w * sc[3] + sh[3];
        ((float4*)X)[j] = v;
    }
}

// ---------------- host orchestration ---------------------------------------
static void mm4(const float* A, int Ald, const float* W, int Wld,
                const float* bias, const float* res, float* C, int Cld,
                int M, int relu,
                const float* Asc = nullptr, const float* Ash = nullptr,
                const float* Zrow = nullptr,
                const float* Rsc = nullptr, const float* Rsh = nullptr,
                double* sumP = nullptr, double* sqP = nullptr)
{
    int tiles = (M + 127) / 128;
    int grid = tiles < 296 ? tiles : 296;
    k_mmgemm<4><<<grid, 256, 110592>>>(A, Ald, W, Wld, bias, res, C, Cld, M, relu,
                                       Asc, Ash, Zrow, Rsc, Rsh, sumP, sqP);
}

static void mm8(const float* A, int Ald, const float* W, int Wld,
                const float* bias, const float* res, float* C, int Cld,
                int M,
                const float* Rsc, const float* Rsh,
                double* sumP, double* sqP)
{
    int tiles = (M + 127) / 128;
    int grid = tiles < 148 ? tiles : 148;
    k_mmgemm<8><<<grid, 256, 176128>>>(A, Ald, W, Wld, bias, res, C, Cld, M, 0,
                                       nullptr, nullptr, nullptr, Rsc, Rsh, sumP, sqP);
}

extern "C" void kernel_launch(void* const* d_in, const int* in_sizes, int n_in,
                              void* d_out, int out_size)
{
    const float* h   = (const float*)d_in[0];
    const float* e   = (const float*)d_in[1];
    const int*   src = (const int*)d_in[2];
    const int*   dst = (const int*)d_in[3];
    const float* WQ  = (const float*)d_in[4];   const float* bQ  = (const float*)d_in[5];
    const float* WK  = (const float*)d_in[6];   const float* bK  = (const float*)d_in[7];
    const float* WV  = (const float*)d_in[8];   const float* bV  = (const float*)d_in[9];
    const float* WE  = (const float*)d_in[10];  const float* bE  = (const float*)d_in[11];
    const float* WOh = (const float*)d_in[12];  const float* bOh = (const float*)d_in[13];
    const float* WOe = (const float*)d_in[14];  const float* bOe = (const float*)d_in[15];
    const float* Wh1 = (const float*)d_in[16];  const float* bh1 = (const float*)d_in[17];
    const float* Wh2 = (const float*)d_in[18];  const float* bh2 = (const float*)d_in[19];
    const float* We1 = (const float*)d_in[20];  const float* be1 = (const float*)d_in[21];
    const float* We2 = (const float*)d_in[22];  const float* be2 = (const float*)d_in[23];
    const float* g1h = (const float*)d_in[24];
    const float* g1e = (const float*)d_in[25];
    const float* g2h = (const float*)d_in[26];
    const float* g2e = (const float*)d_in[27];
    const float* b1h = (const float*)d_in[28];
    const float* b1e = (const float*)d_in[29];
    const float* b2h = (const float*)d_in[30];
    const float* b2e = (const float*)d_in[31];

    float *pQ, *pK, *pV, *ph1, *phidh, *pEA, *pe1, *phide, *pbnsc, *pbnsh, *pwV, *pz;
    double *psum, *psq;
    cudaGetSymbolAddress((void**)&pQ,    g_Q);
    cudaGetSymbolAddress((void**)&pK,    g_K);
    cudaGetSymbolAddress((void**)&pV,    g_V);
    cudaGetSymbolAddress((void**)&ph1,   g_h1);
    cudaGetSymbolAddress((void**)&phidh, g_hidh);
    cudaGetSymbolAddress((void**)&pEA,   g_EA);
    cudaGetSymbolAddress((void**)&pe1,   g_e1);
    cudaGetSymbolAddress((void**)&phide, g_hide);
    cudaGetSymbolAddress((void**)&pbnsc, g_bnsc);
    cudaGetSymbolAddress((void**)&pbnsh, g_bnsh);
    cudaGetSymbolAddress((void**)&pwV,   g_wV);
    cudaGetSymbolAddress((void**)&pz,    g_z);
    cudaGetSymbolAddress((void**)&psum,  g_sum);
    cudaGetSymbolAddress((void**)&psq,   g_sq);

    cudaFuncSetAttribute(k_mmgemm<4>, cudaFuncAttributeMaxDynamicSharedMemorySize, 110592);
    cudaFuncSetAttribute(k_mmgemm<8>, cudaFuncAttributeMaxDynamicSharedMemorySize, 176128);
    cudaFuncSetAttribute(k_ffn1,      cudaFuncAttributeMaxDynamicSharedMemorySize, 208896);

    float* out_h = (float*)d_out;                       // [NN,128]
    float* out_e = (float*)d_out + (size_t)NN * 128;    // [EG,128]

    // 0) zero accumulators + BN stats
    k_zero<<<4096, 256>>>();

    // 1) projections
    mm4(h, 128, WQ, 128, bQ, nullptr, pQ,  128, NN, 0);
    mm4(h, 128, WK, 128, bK, nullptr, pK,  128, NN, 0);
    mm4(h, 128, WV, 128, bV, nullptr, pV,  128, NN, 0);
    mm4(e, 128, WE, 128, bE, nullptr, pEA, 128, EG, 0);

    // 2) edge scores + attention weights + segment sums (atomics)
    k_edge<<<EG / 2, 256>>>(src, dst);

    // 3+4) O projections with residual; h_attn division fused via Zrow,
    //      BN1 column-stat reduce fused into epilogues
    mm4(pwV, 128, WOh, 128, bOh, h, ph1, 128, NN, 0,
        nullptr, nullptr, pz, nullptr, nullptr, psum + 0,   psq + 0);
    mm4(pEA, 128, WOe, 128, bOe, e, pe1, 128, EG, 0,
        nullptr, nullptr, nullptr, nullptr, nullptr, psum + 128, psq + 128);

    // 5) BN #1 finalize
    k_bn_finalize<<<1, 128>>>(0, (float)NN, g1h, b1h);
    k_bn_finalize<<<1, 128>>>(1, (float)EG, g1e, b1e);

    // 6) FFNs: FFN1 single N=256 launch (BN1 on A), FFN2 single K=256 launch
    //    (BN1 on res, BN2 stats fused)
    {
        int gh = (NN + 127) / 128; if (gh > 148) gh = 148;
        k_ffn1<<<gh, 256, 208896>>>(ph1, Wh1, bh1, phidh, NN, pbnsc + 0, pbnsh + 0);
    }
    mm8(phidh, 256, Wh2, 128, bh2, ph1, out_h, 128, NN,
        pbnsc + 0, pbnsh + 0, psum + 256, psq + 256);
    {
        int ge = (EG + 127) / 128; if (ge > 148) ge = 148;
        k_ffn1<<<ge, 256, 208896>>>(pe1, We1, be1, phide, EG, pbnsc + 128, pbnsh + 128);
    }
    mm8(phide, 256, We2, 128, be2, pe1, out_e, 128, EG,
        pbnsc + 128, pbnsh + 128, psum + 384, psq + 384);

    // 7) BN #2 finalize + apply (in place on output)
    k_bn_finalize<<<1, 128>>>(2, (float)NN, g2h, b2h);
    k_bn_apply<<<12800, 256>>>(out_h, (size_t)NN, 2);
    k_bn_finalize<<<1, 128>>>(3, (float)EG, g2e, b2e);
    k_bn_apply<<<100000, 256>>>(out_e, (size_t)EG, 3);
}

// round 8
// speedup vs baseline: 1.4967x; 1.1284x over previous
#include <cuda_runtime.h>
#include <cuda_bf16.h>
#include <cstdint>
#include <math.h>

// Problem constants
#define NN 50000
#define EG 800000

// ---------------- scratch (device globals; no runtime allocation) ----------
__device__ float  g_Q   [(size_t)NN * 128];
__device__ float  g_K   [(size_t)NN * 128];
__device__ float  g_V   [(size_t)NN * 128];
__device__ float  g_h1  [(size_t)NN * 128];
__device__ float  g_hidh[(size_t)NN * 256];
__device__ float  g_wV  [(size_t)NN * 128];
__device__ float  g_z   [(size_t)NN * 8];
__device__ float  g_EA  [(size_t)EG * 128];
__device__ float  g_e1  [(size_t)EG * 128];
__device__ float  g_hide[(size_t)EG * 256];
__device__ double g_sum [4 * 128];
__device__ double g_sq  [4 * 128];
__device__ float  g_bnsc[4 * 128];
__device__ float  g_bnsh[4 * 128];

// pre-split weights: hi plane [0, TOTW), lo plane [TOTW, 2*TOTW), bf16
#define OFF_WQ   0
#define OFF_WK   16384
#define OFF_WV   32768
#define OFF_WE   49152
#define OFF_WOH  65536
#define OFF_WOE  81920
#define OFF_WH1  98304
#define OFF_WE1  131072
#define OFF_WH2  163840
#define OFF_WE2  196608
#define TOTW     229376
__device__ __nv_bfloat16 g_Wb[2 * TOTW];

// ---------------- zero accumulators ----------------------------------------
__global__ void k_zero() {
    size_t i = (size_t)blockIdx.x * blockDim.x + threadIdx.x;
    size_t stride = (size_t)gridDim.x * blockDim.x;
    for (size_t j = i; j < (size_t)NN * 128; j += stride) g_wV[j] = 0.f;
    for (size_t j = i; j < (size_t)NN * 8;   j += stride) g_z[j]  = 0.f;
    if (i < 512) { g_sum[i] = 0.0; g_sq[i] = 0.0; }
}

// ============================================================================
// helpers
// ============================================================================
__device__ __forceinline__ uint32_t smem_u32(const void* p) {
    uint32_t a;
    asm("{ .reg .u64 t; cvta.to.shared.u64 t, %1; cvt.u32.u64 %0, t; }"
        : "=r"(a) : "l"(p));
    return a;
}

__device__ __forceinline__ void ldsm_x4(uint32_t addr, uint32_t* r) {
    asm volatile("ldmatrix.sync.aligned.m8n8.x4.shared.b16 {%0,%1,%2,%3}, [%4];"
        : "=r"(r[0]), "=r"(r[1]), "=r"(r[2]), "=r"(r[3]) : "r"(addr));
}

__device__ __forceinline__ void mma_bf16(float* acc, const uint32_t* a, const uint32_t* b) {
    asm volatile(
        "mma.sync.aligned.m16n8k16.row.col.f32.bf16.bf16.f32 "
        "{%0,%1,%2,%3},{%4,%5,%6,%7},{%8,%9},{%0,%1,%2,%3};"
        : "+f"(acc[0]), "+f"(acc[1]), "+f"(acc[2]), "+f"(acc[3])
        : "r"(a[0]), "r"(a[1]), "r"(a[2]), "r"(a[3]), "r"(b[0]), "r"(b[1]));
}

__device__ __forceinline__ void split_pair(float x0, float x1, uint32_t& hi, uint32_t& lo)
{
    __nv_bfloat162 h = __floats2bfloat162_rn(x0, x1);
    float r0 = x0 - __bfloat162float(__low2bfloat16(h));
    float r1 = x1 - __bfloat162float(__high2bfloat16(h));
    __nv_bfloat162 l = __floats2bfloat162_rn(r0, r1);
    hi = *reinterpret_cast<uint32_t*>(&h);
    lo = *reinterpret_cast<uint32_t*>(&l);
}

// ============================================================================
// Weight pre-split: all 10 matrices fp32 [k][n] -> bf16 hi/lo planes at [n][k]
// ============================================================================
__global__ __launch_bounds__(256)
void k_wsplit(const float* __restrict__ WQ,  const float* __restrict__ WK,
              const float* __restrict__ WV,  const float* __restrict__ WE,
              const float* __restrict__ WOh, const float* __restrict__ WOe,
              const float* __restrict__ Wh1, const float* __restrict__ We1,
              const float* __restrict__ Wh2, const float* __restrict__ We2)
{
    int p = blockIdx.x * 256 + threadIdx.x;      // pair index, 114688 total
    if (p >= TOTW / 2) return;
    const float* W;
    int Kd, Nd, local, base;
    if (p < 49152) {                              // six 128x128 mats
        int m = p >> 13;                          // 8192 pairs each
        local = p & 8191;
        Kd = 128; Nd = 128; base = m << 14;
        W = (m == 0) ? WQ : (m == 1) ? WK : (m == 2) ? WV :
            (m == 3) ? WE : (m == 4) ? WOh : WOe;
    } else if (p < 65536)  { local = p - 49152; Kd = 128; Nd = 256; base = OFF_WH1; W = Wh1; }
    else if (p < 81920)    { local = p - 65536; Kd = 128; Nd = 256; base = OFF_WE1; W = We1; }
    else if (p < 98304)    { local = p - 81920; Kd = 256; Nd = 128; base = OFF_WH2; W = Wh2; }
    else                   { local = p - 98304; Kd = 256; Nd = 128; base = OFF_WE2; W = We2; }
    int n  = local % Nd;
    int k  = (local / Nd) * 2;
    float x0 = W[(size_t)k * Nd + n];
    float x1 = W[(size_t)(k + 1) * Nd + n];
    uint32_t hi, lo;
    split_pair(x0, x1, hi, lo);
    size_t o = (size_t)base + (size_t)n * Kd + k;
    *(uint32_t*)((char*)g_Wb + o * 2)              = hi;
    *(uint32_t*)((char*)g_Wb + (o + TOTW) * 2)     = lo;
}

// ============================================================================
// Pipelined HMMA bf16 3-split GEMM. K = KC*32 (KC=4 or 8), N-tile = 128.
//   C = [res(*RscRsh) +] (A(*AscAsh)(/Zrow)) @ W + bias (, relu)
// W pre-split bf16 hi/lo at [n][K] (row-major, contiguous).
// ============================================================================
#define A_CH_B 10240
#define A_BUF_B 20480
#define B_BASE 40960

template<int KC>
__global__ __launch_bounds__(256, (KC == 4) ? 2 : 1)
void k_mmgemm(const float* __restrict__ A, int Ald,
              const __nv_bfloat16* __restrict__ Whi,
              const __nv_bfloat16* __restrict__ Wlo,
              const float* __restrict__ bias, const float* __restrict__ res,
              float* __restrict__ C, int Cld, int M, int relu,
              const float* __restrict__ Asc, const float* __restrict__ Ash,
              const float* __restrict__ Zrow,
              const float* __restrict__ Rsc, const float* __restrict__ Rsh,
              double* sumP, double* sqP)
{
    extern __shared__ char smem[];
    constexpr int K  = KC * 32;
    constexpr int BS = K + 8;
    constexpr int KSH = (KC == 4) ? 4 : 5;       // log2(K/8)
    constexpr uint32_t BBs = 128u * BS * 2u;
    const uint32_t sbase = smem_u32(smem);

    const int tid  = threadIdx.x;
    const int lane = tid & 31;
    const int wid  = tid >> 5;
    const int wm   = wid >> 2;
    const int wn   = wid & 3;

    // ---- copy pre-split W into smem (coalesced uint4)
    for (int i = tid; i < 128 * (K >> 3); i += 256) {
        int k8 = i & ((K >> 3) - 1);
        int n  = i >> KSH;
        uint4 vh = *(const uint4*)(Whi + (size_t)n * K + (k8 << 3));
        uint4 vl = *(const uint4*)(Wlo + (size_t)n * K + (k8 << 3));
        uint32_t off = ((uint32_t)n * BS + (k8 << 3)) * 2u;
        *(uint4*)(smem + B_BASE + off)       = vh;
        *(uint4*)(smem + B_BASE + BBs + off) = vl;
    }

    const int tiles = (M + 127) >> 7;
    const int a_row = (lane & 15);
    const int a_k   = (lane >> 4) << 3;
    const int b_row = (lane & 7) + ((lane >> 4) << 3);
    const int b_k   = ((lane >> 3) & 1) << 3;

    float4 pf[4];
    int t = blockIdx.x;
    if (t < tiles) {
        int m0 = t << 7;
        #pragma unroll
        for (int j = 0; j < 4; j++) {
            int idx = tid + (j << 8);
            int gm = m0 + (idx >> 3); if (gm > M - 1) gm = M - 1;
            pf[j] = *(const float4*)(A + (size_t)gm * Ald + ((idx & 7) << 2));
        }
    }
    int buf = 0;

    for (; t < tiles; t += gridDim.x) {
        const int m0 = t << 7;
        float acc[4][4][4] = {};
        for (int kc = 0; kc < KC; kc++) {
            const int kb = kc << 5;
            {
                char* ah_base = smem + buf * A_BUF_B;
                #pragma unroll
                for (int j = 0; j < 4; j++) {
                    int idx = tid + (j << 8);
                    int row = idx >> 3;
                    int c4  = (idx & 7) << 2;
                    float4 v = pf[j];
                    if (Asc) {
                        float4 sc = *(const float4*)(Asc + kb + c4);
                        float4 sh = *(const float4*)(Ash + kb + c4);
                        v.x = v.x * sc.x + sh.x;
                        v.y = v.y * sc.y + sh.y;
                        v.z = v.z * sc.z + sh.z;
                        v.w = v.w * sc.w + sh.w;
                    }
                    if (Zrow) {
                        int gm = m0 + row; if (gm > M - 1) gm = M - 1;
                        float zz = 1.0f / (Zrow[(size_t)gm * 8 + ((kb + c4) >> 4)] + 1e-6f);
                        v.x *= zz; v.y *= zz; v.z *= zz; v.w *= zz;
                    }
                    uint32_t h01, l01, h23, l23;
                    split_pair(v.x, v.y, h01, l01);
                    split_pair(v.z, v.w, h23, l23);
                    uint32_t off = ((uint32_t)row * 40 + c4) * 2u;
                    *(uint2*)(ah_base + off)          = make_uint2(h01, h23);
                    *(uint2*)(ah_base + A_CH_B + off) = make_uint2(l01, l23);
                }
            }
            __syncthreads();
            {
                int kc2 = kc + 1, tn = t;
                if (kc2 == KC) { kc2 = 0; tn = t + gridDim.x; }
                if (tn < tiles) {
                    int m2 = tn << 7, kb2 = kc2 << 5;
                    #pragma unroll
                    for (int j = 0; j < 4; j++) {
                        int idx = tid + (j << 8);
                        int gm = m2 + (idx >> 3); if (gm > M - 1) gm = M - 1;
                        pf[j] = *(const float4*)(A + (size_t)gm * Ald + kb2 + ((idx & 7) << 2));
                    }
                }
            }
            const uint32_t abase = sbase + buf * A_BUF_B;
            #pragma unroll
            for (int ks = 0; ks < 2; ks++) {
                const int ka = ks << 4;
                uint32_t bh[4][2], bl[4][2];
                #pragma unroll
                for (int np = 0; np < 2; np++) {
                    uint32_t roff = ((uint32_t)(wn * 32 + np * 16 + b_row) * BS
                                     + kb + ka + b_k) * 2u;
                    uint32_t rh[4], rl[4];
                    ldsm_x4(sbase + B_BASE + roff, rh);
                    ldsm_x4(sbase + B_BASE + BBs + roff, rl);
                    bh[np*2][0] = rh[0]; bh[np*2][1] = rh[1];
                    bh[np*2+1][0] = rh[2]; bh[np*2+1][1] = rh[3];
                    bl[np*2][0] = rl[0]; bl[np*2][1] = rl[1];
                    bl[np*2+1][0] = rl[2]; bl[np*2+1][1] = rl[3];
                }
                uint32_t ah[4][4], al[4][4];
                #pragma unroll
                for (int mt = 0; mt < 4; mt++) {
                    uint32_t roff = ((uint32_t)(wm * 64 + mt * 16 + a_row) * 40
                                     + ka + a_k) * 2u;
                    ldsm_x4(abase + roff, ah[mt]);
                    ldsm_x4(abase + A_CH_B + roff, al[mt]);
                }
                #pragma unroll
                for (int mt = 0; mt < 4; mt++)
                    #pragma unroll
                    for (int nt = 0; nt < 4; nt++) {
                        mma_bf16(acc[mt][nt], ah[mt], bh[nt]);
                        mma_bf16(acc[mt][nt], ah[mt], bl[nt]);
                        mma_bf16(acc[mt][nt], al[mt], bh[nt]);
                    }
            }
            buf ^= 1;
        }

        const int g  = lane >> 2;
        const int t2 = (lane & 3) << 1;
        #pragma unroll
        for (int nt = 0; nt < 4; nt++) {
            int c0 = wn * 32 + nt * 8 + t2;
            float2 bv = *(const float2*)(bias + c0);
            float2 rs = make_float2(1.f, 1.f), rb = make_float2(0.f, 0.f);
            if (Rsc) {
                rs = *(const float2*)(Rsc + c0);
                rb = *(const float2*)(Rsh + c0);
            }
            float ps0 = 0.f, ps1 = 0.f, q0 = 0.f, q1 = 0.f;
            #pragma unroll
            for (int mt = 0; mt < 4; mt++) {
                #pragma unroll
                for (int half = 0; half < 2; half++) {
                    int r = m0 + wm * 64 + mt * 16 + g + half * 8;
                    float2 v = make_float2(acc[mt][nt][half*2]   + bv.x,
                                           acc[mt][nt][half*2+1] + bv.y);
                    if (r < M) {
                        size_t o = (size_t)r * Cld + c0;
                        if (res) {
                            float2 rv = *(const float2*)(res + o);
                            v.x += rv.x * rs.x + rb.x;
                            v.y += rv.y * rs.y + rb.y;
                        }
                        if (relu) { v.x = fmaxf(v.x, 0.f); v.y = fmaxf(v.y, 0.f); }
                        *(float2*)(C + o) = v;
                    } else { v.x = 0.f; v.y = 0.f; }
                    ps0 += v.x; q0 += v.x * v.x;
                    ps1 += v.y; q1 += v.y * v.y;
                }
            }
            if (sumP) {
                #pragma unroll
                for (int off = 16; off >= 4; off >>= 1) {
                    ps0 += __shfl_down_sync(0xffffffffu, ps0, off);
                    ps1 += __shfl_down_sync(0xffffffffu, ps1, off);
                    q0  += __shfl_down_sync(0xffffffffu, q0,  off);
                    q1  += __shfl_down_sync(0xffffffffu, q1,  off);
                }
                if (lane < 4) {
                    int cc = wn * 32 + nt * 8 + lane * 2;
                    atomicAdd(&sumP[cc],     (double)ps0);
                    atomicAdd(&sumP[cc + 1], (double)ps1);
                    atomicAdd(&sqP[cc],      (double)q0);
                    atomicAdd(&sqP[cc + 1],  (double)q1);
                }
            }
        }
    }
}

// ============================================================================
// FFN1: C[M,256] = relu( (A(*AscAsh)) @ W[128,256] + bias ), single launch.
// W pre-split bf16 hi/lo at [n=256][k=128].
// ============================================================================
#define F1_A_LO 34816
#define F1_B    69632
#define F1_BBs  69632u

__global__ __launch_bounds__(256, 1)
void k_ffn1(const float* __restrict__ A,
            const __nv_bfloat16* __restrict__ Whi,
            const __nv_bfloat16* __restrict__ Wlo,
            const float* __restrict__ bias, float* __restrict__ C, int M,
            const float* __restrict__ Asc, const float* __restrict__ Ash)
{
    extern __shared__ char smem[];
    const uint32_t sbase = smem_u32(smem);
    const int tid  = threadIdx.x;
    const int lane = tid & 31;
    const int wid  = tid >> 5;
    const int wm   = wid >> 2;
    const int wn   = wid & 3;

    // ---- copy pre-split W [256][128] into smem rows of 136
    for (int i = tid; i < 256 * 16; i += 256) {
        int k8 = i & 15;
        int n  = i >> 4;
        uint4 vh = *(const uint4*)(Whi + (size_t)n * 128 + (k8 << 3));
        uint4 vl = *(const uint4*)(Wlo + (size_t)n * 128 + (k8 << 3));
        uint32_t off = ((uint32_t)n * 136 + (k8 << 3)) * 2u;
        *(uint4*)(smem + F1_B + off)          = vh;
        *(uint4*)(smem + F1_B + F1_BBs + off) = vl;
    }

    const int tiles = (M + 127) >> 7;
    const int a_row = (lane & 15);
    const int a_k   = (lane >> 4) << 3;
    const int b_row = (lane & 7) + ((lane >> 4) << 3);
    const int b_k   = ((lane >> 3) & 1) << 3;
    const int g  = lane >> 2;
    const int t2 = (lane & 3) << 1;

    for (int t = blockIdx.x; t < tiles; t += gridDim.x) {
        const int m0 = t << 7;
        __syncthreads();
        for (int j = 0; j < 16; j++) {
            int idx = tid + (j << 8);
            int row = idx >> 5;
            int c4  = (idx & 31) << 2;
            int gm = m0 + row; if (gm > M - 1) gm = M - 1;
            float4 v = *(const float4*)(A + (size_t)gm * 128 + c4);
            float4 sc = *(const float4*)(Asc + c4);
            float4 sh = *(const float4*)(Ash + c4);
            v.x = v.x * sc.x + sh.x;
            v.y = v.y * sc.y + sh.y;
            v.z = v.z * sc.z + sh.z;
            v.w = v.w * sc.w + sh.w;
            uint32_t h01, l01, h23, l23;
            split_pair(v.x, v.y, h01, l01);
            split_pair(v.z, v.w, h23, l23);
            uint32_t off = ((uint32_t)row * 136 + c4) * 2u;
            *(uint2*)(smem + off)           = make_uint2(h01, h23);
            *(uint2*)(smem + F1_A_LO + off) = make_uint2(l01, l23);
        }
        __syncthreads();

        for (int nh = 0; nh < 2; nh++) {
            float acc[4][4][4] = {};
            #pragma unroll
            for (int ks = 0; ks < 8; ks++) {
                const int ka = ks << 4;
                uint32_t bh[4][2], bl[4][2];
                #pragma unroll
                for (int np = 0; np < 2; np++) {
                    uint32_t roff = ((uint32_t)(nh * 128 + wn * 32 + np * 16 + b_row) * 136
                                     + ka + b_k) * 2u;
                    uint32_t rh[4], rl[4];
                    ldsm_x4(sbase + F1_B + roff, rh);
                    ldsm_x4(sbase + F1_B + F1_BBs + roff, rl);
                    bh[np*2][0] = rh[0]; bh[np*2][1] = rh[1];
                    bh[np*2+1][0] = rh[2]; bh[np*2+1][1] = rh[3];
                    bl[np*2][0] = rl[0]; bl[np*2][1] = rl[1];
                    bl[np*2+1][0] = rl[2]; bl[np*2+1][1] = rl[3];
                }
                uint32_t ah[4][4], al[4][4];
                #pragma unroll
                for (int mt = 0; mt < 4; mt++) {
                    uint32_t roff = ((uint32_t)(wm * 64 + mt * 16 + a_row) * 136
                                     + ka + a_k) * 2u;
                    ldsm_x4(sbase + roff, ah[mt]);
                    ldsm_x4(sbase + F1_A_LO + roff, al[mt]);
                }
                #pragma unroll
                for (int mt = 0; mt < 4; mt++)
                    #pragma unroll
                    for (int nt = 0; nt < 4; nt++) {
                        mma_bf16(acc[mt][nt], ah[mt], bh[nt]);
                        mma_bf16(acc[mt][nt], ah[mt], bl[nt]);
                        mma_bf16(acc[mt][nt], al[mt], bh[nt]);
                    }
            }
            #pragma unroll
            for (int mt = 0; mt < 4; mt++) {
                int r0 = m0 + wm * 64 + mt * 16 + g;
                #pragma unroll
                for (int nt = 0; nt < 4; nt++) {
                    int c0 = nh * 128 + wn * 32 + nt * 8 + t2;
                    float2 bv = *(const float2*)(bias + c0);
                    #pragma unroll
                    for (int half = 0; half < 2; half++) {
                        int r = r0 + half * 8;
                        if (r >= M) continue;
                        float2 v = make_float2(
                            fmaxf(acc[mt][nt][half*2]   + bv.x, 0.f),
                            fmaxf(acc[mt][nt][half*2+1] + bv.y, 0.f));
                        *(float2*)(C + (size_t)r * 256 + c0) = v;
                    }
                }
            }
        }
    }
}

// ---------------- edge kernel: 4-edge batched, hoisted gathers ---------------
__global__ __launch_bounds__(256)
void k_edge(const int* __restrict__ src, const int* __restrict__ dst)
{
    const int t  = threadIdx.x & 127;
    const int e0 = blockIdx.x * 8 + (threadIdx.x >> 7) * 4;
    int s[4], d[4];
    #pragma unroll
    for (int i = 0; i < 4; i++) { s[i] = src[e0 + i]; d[i] = dst[e0 + i]; }
    float kv[4], qv[4], vv[4], ev[4];
    #pragma unroll
    for (int i = 0; i < 4; i++) {
        kv[i] = g_K[(size_t)s[i] * 128 + t];
        qv[i] = g_Q[(size_t)d[i] * 128 + t];
        vv[i] = g_V[(size_t)s[i] * 128 + t];
        ev[i] = g_EA[(size_t)(e0 + i) * 128 + t];
    }
    #pragma unroll
    for (int i = 0; i < 4; i++) {
        float sc = kv[i] * qv[i] * 0.25f * ev[i];
        g_EA[(size_t)(e0 + i) * 128 + t] = sc;
        float sum = sc;
        #pragma unroll
        for (int off = 8; off; off >>= 1)
            sum += __shfl_xor_sync(0xffffffffu, sum, off, 16);
        sum = fminf(fmaxf(sum, -5.f), 5.f);
        float ss = __expf(sum);
        atomicAdd(&g_wV[(size_t)d[i] * 128 + t], vv[i] * ss);
        if ((t & 15) == 0)
            atomicAdd(&g_z[(size_t)d[i] * 8 + (t >> 4)], ss);
    }
}

// ---------------- batch-norm finalize / apply --------------------------------
__global__ void k_bn_finalize(int slot, float Mf,
                              const float* __restrict__ g, const float* __restrict__ b)
{
    int c = threadIdx.x;
    double mu  = g_sum[slot * 128 + c] / (double)Mf;
    double var = g_sq [slot * 128 + c] / (double)Mf - mu * mu;
    float sc = g[c] * rsqrtf((float)var + 1e-5f);
    g_bnsc[slot * 128 + c] = sc;
    g_bnsh[slot * 128 + c] = b[c] - (float)mu * sc;
}

__global__ __launch_bounds__(256)
void k_bn_apply(float* __restrict__ X, size_t M, int slot)
{
    size_t total4 = M * 32;
    size_t i = (size_t)blockIdx.x * blockDim.x + threadIdx.x;
    size_t stride = (size_t)gridDim.x * blockDim.x;
    for (size_t j = i; j < total4; j += stride) {
        int c = (int)(j & 31) * 4;
        const float* sc = g_bnsc + slot * 128 + c;
        const float* sh = g_bnsh + slot * 128 + c;
        float4 v = ((float4*)X)[j];
        v.x = v.x * sc[0] + sh[0];
        v.y = v.y * sc[1] + sh[1];
        v.z = v.z * sc[2] + sh[2];
        v.w = v.w * sc[3] + sh[3];
        ((float4*)X)[j] = v;
    }
}

// ---------------- host orchestration ---------------------------------------
static __nv_bfloat16* wb_base = nullptr;

static void mm4(const float* A, int Ald, int woff,
                const float* bias, const float* res, float* C, int Cld,
                int M, int relu,
                const float* Asc = nullptr, const float* Ash = nullptr,
                const float* Zrow = nullptr,
                const float* Rsc = nullptr, const float* Rsh = nullptr,
                double* sumP = nullptr, double* sqP = nullptr)
{
    int tiles = (M + 127) / 128;
    int grid = tiles < 296 ? tiles : 296;
    k_mmgemm<4><<<grid, 256, 110592>>>(A, Ald, wb_base + woff, wb_base + woff + TOTW,
                                       bias, res, C, Cld, M, relu,
                                       Asc, Ash, Zrow, Rsc, Rsh, sumP, sqP);
}

static void mm8(const float* A, int Ald, int woff,
                const float* bias, const float* res, float* C, int Cld,
                int M,
                const float* Rsc, const float* Rsh,
                double* sumP, double* sqP)
{
    int tiles = (M + 127) / 128;
    int grid = tiles < 148 ? tiles : 148;
    k_mmgemm<8><<<grid, 256, 176128>>>(A, Ald, wb_base + woff, wb_base + woff + TOTW,
                                       bias, res, C, Cld, M, 0,
                                       nullptr, nullptr, nullptr, Rsc, Rsh, sumP, sqP);
}

extern "C" void kernel_launch(void* const* d_in, const int* in_sizes, int n_in,
                              void* d_out, int out_size)
{
    const float* h   = (const float*)d_in[0];
    const float* e   = (const float*)d_in[1];
    const int*   src = (const int*)d_in[2];
    const int*   dst = (const int*)d_in[3];
    const float* WQ  = (const float*)d_in[4];   const float* bQ  = (const float*)d_in[5];
    const float* WK  = (const float*)d_in[6];   const float* bK  = (const float*)d_in[7];
    const float* WV  = (const float*)d_in[8];   const float* bV  = (const float*)d_in[9];
    const float* WE  = (const float*)d_in[10];  const float* bE  = (const float*)d_in[11];
    const float* WOh = (const float*)d_in[12];  const float* bOh = (const float*)d_in[13];
    const float* WOe = (const float*)d_in[14];  const float* bOe = (const float*)d_in[15];
    const float* Wh1 = (const float*)d_in[16];  const float* bh1 = (const float*)d_in[17];
    const float* Wh2 = (const float*)d_in[18];  const float* bh2 = (const float*)d_in[19];
    const float* We1 = (const float*)d_in[20];  const float* be1 = (const float*)d_in[21];
    const float* We2 = (const float*)d_in[22];  const float* be2 = (const float*)d_in[23];
    const float* g1h = (const float*)d_in[24];
    const float* g1e = (const float*)d_in[25];
    const float* g2h = (const float*)d_in[26];
    const float* g2e = (const float*)d_in[27];
    const float* b1h = (const float*)d_in[28];
    const float* b1e = (const float*)d_in[29];
    const float* b2h = (const float*)d_in[30];
    const float* b2e = (const float*)d_in[31];

    float *pQ, *pK, *pV, *ph1, *phidh, *pEA, *pe1, *phide, *pbnsc, *pbnsh, *pwV, *pz;
    double *psum, *psq;
    cudaGetSymbolAddress((void**)&pQ,    g_Q);
    cudaGetSymbolAddress((void**)&pK,    g_K);
    cudaGetSymbolAddress((void**)&pV,    g_V);
    cudaGetSymbolAddress((void**)&ph1,   g_h1);
    cudaGetSymbolAddress((void**)&phidh, g_hidh);
    cudaGetSymbolAddress((void**)&pEA,   g_EA);
    cudaGetSymbolAddress((void**)&pe1,   g_e1);
    cudaGetSymbolAddress((void**)&phide, g_hide);
    cudaGetSymbolAddress((void**)&pbnsc, g_bnsc);
    cudaGetSymbolAddress((void**)&pbnsh, g_bnsh);
    cudaGetSymbolAddress((void**)&pwV,   g_wV);
    cudaGetSymbolAddress((void**)&pz,    g_z);
    cudaGetSymbolAddress((void**)&psum,  g_sum);
    cudaGetSymbolAddress((void**)&psq,   g_sq);
    cudaGetSymbolAddress((void**)&wb_base, g_Wb);

    cudaFuncSetAttribute(k_mmgemm<4>, cudaFuncAttributeMaxDynamicSharedMemorySize, 110592);
    cudaFuncSetAttribute(k_mmgemm<8>, cudaFuncAttributeMaxDynamicSharedMemorySize, 176128);
    cudaFuncSetAttribute(k_ffn1,      cudaFuncAttributeMaxDynamicSharedMemorySize, 208896);

    float* out_h = (float*)d_out;
    float* out_e = (float*)d_out + (size_t)NN * 128;

    // 0) zero accumulators + BN stats; pre-split weights
    k_zero<<<4096, 256>>>();
    k_wsplit<<<448, 256>>>(WQ, WK, WV, WE, WOh, WOe, Wh1, We1, Wh2, We2);

    // 1) projections
    mm4(h, 128, OFF_WQ, bQ, nullptr, pQ,  128, NN, 0);
    mm4(h, 128, OFF_WK, bK, nullptr, pK,  128, NN, 0);
    mm4(h, 128, OFF_WV, bV, nullptr, pV,  128, NN, 0);
    mm4(e, 128, OFF_WE, bE, nullptr, pEA, 128, EG, 0);

    // 2) edge scores + attention weights + segment sums
    k_edge<<<EG / 8, 256>>>(src, dst);

    // 3+4) O projections; h_attn fused via Zrow; BN1 stats fused
    mm4(pwV, 128, OFF_WOH, bOh, h, ph1, 128, NN, 0,
        nullptr, nullptr, pz, nullptr, nullptr, psum + 0,   psq + 0);
    mm4(pEA, 128, OFF_WOE, bOe, e, pe1, 128, EG, 0,
        nullptr, nullptr, nullptr, nullptr, nullptr, psum + 128, psq + 128);

    // 5) BN #1 finalize
    k_bn_finalize<<<1, 128>>>(0, (float)NN, g1h, b1h);
    k_bn_finalize<<<1, 128>>>(1, (float)EG, g1e, b1e);

    // 6) FFNs
    {
        int gh = (NN + 127) / 128; if (gh > 148) gh = 148;
        k_ffn1<<<gh, 256, 208896>>>(ph1, wb_base + OFF_WH1, wb_base + OFF_WH1 + TOTW,
                                    bh1, phidh, NN, pbnsc + 0, pbnsh + 0);
    }
    mm8(phidh, 256, OFF_WH2, bh2, ph1, out_h, 128, NN,
        pbnsc + 0, pbnsh + 0, psum + 256, psq + 256);
    {
        int ge = (EG + 127) / 128; if (ge > 148) ge = 148;
        k_ffn1<<<ge, 256, 208896>>>(pe1, wb_base + OFF_WE1, wb_base + OFF_WE1 + TOTW,
                                    be1, phide, EG, pbnsc + 128, pbnsh + 128);
    }
    mm8(phide, 256, OFF_WE2, be2, pe1, out_e, 128, EG,
        pbnsc + 128, pbnsh + 128, psum + 384, psq + 384);

    // 7) BN #2 finalize + apply
    k_bn_finalize<<<1, 128>>>(2, (float)NN, g2h, b2h);
    k_bn_apply<<<12800, 256>>>(out_h, (size_t)NN, 2);
    k_bn_finalize<<<1, 128>>>(3, (float)EG, g2e, b2e);
    k_bn_apply<<<100000, 256>>>(out_e, (size_t)EG, 3);
}